// round 3
// baseline (speedup 1.0000x reference)
#include <cuda_runtime.h>

typedef unsigned long long ull;

#define T_LEN 8192
#define NLAG  64

// skew2 layout: phys(i) = i + 2*(i>>4)  (stride 18 per 16-elem chunk,
// parity-preserving -> logical-even pairs are 8B-aligned LDS.64)
#define PHYS_MAX 9288   // phys(8255)=9285, padded

// ---- packed f32x2 helpers (sm_100+ PTX) ----
__device__ __forceinline__ ull pk(float lo, float hi) {
    ull r;
    asm("mov.b64 %0, {%1, %2};" : "=l"(r) : "f"(lo), "f"(hi));
    return r;
}
__device__ __forceinline__ void fma2(ull& d, ull a, ull b) {
    asm("fma.rn.f32x2 %0, %1, %2, %0;" : "+l"(d) : "l"(a), "l"(b));
}
__device__ __forceinline__ float pksum(ull v) {
    float lo, hi;
    asm("mov.b64 {%0, %1}, %2;" : "=f"(lo), "=f"(hi) : "l"(v));
    return lo + hi;
}

// One lag-group: lags K0..K0+15 (K0 = 1+16g, odd).
// wst: per-warp segment stagger so the 8 warps' load/FMA phases decorrelate.
template<int K0>
__device__ __forceinline__ void corr_group(const float* __restrict__ sm, int tt,
                                           int wst,
                                           ull* __restrict__ acc,
                                           float* __restrict__ eacc)
{
#pragma unroll 2
    for (int s = 0; s < 8; ++s) {
        const int seg  = (s + wst) & 7;
        const int base = seg * 1152 + tt * 18;   // phys(seg*1024 + tt*16)

        // ---- A: 16 contiguous positions, 8 aligned pairs (LDS.64, CF) ----
        float2 A[8];
#pragma unroll
        for (int m = 0; m < 8; ++m)
            A[m] = *reinterpret_cast<const float2*>(&sm[base + 2 * m]);

        // ---- W: 15 aligned pairs covering w[1..30]; pair r starts at even
        // logical u = K0+2r+1; phys = u + 2*(u>>4) (parity preserved) ----
        float2 W[15];
#pragma unroll
        for (int r = 0; r < 15; ++r) {
            const int u = K0 + 2 * r + 1;
            W[r] = *reinterpret_cast<const float2*>(&sm[base + u + 2 * (u >> 4)]);
        }
        const float w0 = sm[base + K0 + 2 * (K0 >> 4)];   // w[0] scalar

        ull Au[8];
#pragma unroll
        for (int m = 0; m < 8; ++m) Au[m] = pk(A[m].x, A[m].y);
        ull Wu[15];
#pragma unroll
        for (int r = 0; r < 15; ++r) Wu[r] = pk(W[r].x, W[r].y);
        const float a0  = A[0].x;
        const float a15 = A[7].y;

        // ---- odd lags dk=2e+1: aligned A-pairs x W-pairs ----
#pragma unroll
        for (int m = 0; m < 8; ++m)
#pragma unroll
            for (int e = 0; e < 8; ++e)
                fma2(acc[2 * e + 1], Au[m], Wu[m + e]);

        // ---- even lags dk=2e: shifted A-pairs (packed) x same W-pairs + edges
        ull Apu[7];
#pragma unroll
        for (int m = 0; m < 7; ++m) Apu[m] = pk(A[m].y, A[m + 1].x);
#pragma unroll
        for (int m = 0; m < 7; ++m)
#pragma unroll
            for (int e = 0; e < 8; ++e)
                fma2(acc[2 * e], Apu[m], Wu[m + e]);
#pragma unroll
        for (int e = 0; e < 8; ++e) {
            const float wE = (e == 0) ? w0 : W[e - 1].y;   // w[2e]
            const float wO = W[e + 7].x;                   // w[15+2e]
            eacc[e] += a0 * wE + a15 * wO;
        }
    }
}

__global__ __launch_bounds__(256, 2)
void autocorr_kernel(const float* __restrict__ X, float* __restrict__ out)
{
    __shared__ __align__(16) float sm[PHYS_MAX];
    __shared__ float red[8][16];
    __shared__ float wsum[8], wsq[8];
    __shared__ float stats[2];   // [0]=mean, [1]=1/var0

    const int tid = threadIdx.x;
    const int b   = blockIdx.x;
    const float4* Xr = reinterpret_cast<const float4*>(X + (size_t)b * T_LEN);

    // ---------------- Phase 1: load, mean & sumsq, centered skewed store
    float4 xv[8];
    float s = 0.f, q = 0.f;
#pragma unroll
    for (int r = 0; r < 8; ++r) {
        xv[r] = Xr[tid + r * 256];
        s += xv[r].x + xv[r].y + xv[r].z + xv[r].w;
        q += xv[r].x * xv[r].x + xv[r].y * xv[r].y
           + xv[r].z * xv[r].z + xv[r].w * xv[r].w;
    }
#pragma unroll
    for (int o = 16; o > 0; o >>= 1) {
        s += __shfl_xor_sync(0xffffffffu, s, o);
        q += __shfl_xor_sync(0xffffffffu, q, o);
    }
    if ((tid & 31) == 0) { wsum[tid >> 5] = s; wsq[tid >> 5] = q; }
    __syncthreads();
    if (tid == 0) {
        float S = 0.f, Q = 0.f;
#pragma unroll
        for (int i = 0; i < 8; ++i) { S += wsum[i]; Q += wsq[i]; }
        float mean = S * (1.f / (float)T_LEN);
        stats[0] = mean;
        stats[1] = 1.f / (Q - (float)T_LEN * mean * mean);  // 1/T cancels in ratio
    }
    __syncthreads();
    const float mean = stats[0];

#pragma unroll
    for (int r = 0; r < 8; ++r) {
        int i0 = (tid + r * 256) * 4;
        int p  = i0 + 2 * (i0 >> 4);        // all 4 elems share the skew
        *reinterpret_cast<float2*>(&sm[p])     = make_float2(xv[r].x - mean, xv[r].y - mean);
        *reinterpret_cast<float2*>(&sm[p + 2]) = make_float2(xv[r].z - mean, xv[r].w - mean);
    }
    if (tid < NLAG) {                       // zero pad -> t<T-k bound handled for free
        int i = T_LEN + tid;
        sm[i + 2 * (i >> 4)] = 0.f;
    }
    __syncthreads();

    // ---------------- Phase 2: lag-group register-tiled correlation
    const int g   = tid >> 6;
    const int tt  = tid & 63;
    const int wst = tid >> 5;               // per-warp segment stagger

    ull acc[16];
#pragma unroll
    for (int i = 0; i < 16; ++i) acc[i] = 0ull;
    float eacc[8];
#pragma unroll
    for (int i = 0; i < 8; ++i) eacc[i] = 0.f;

    switch (g) {
        case 0: corr_group<1 >(sm, tt, wst, acc, eacc); break;
        case 1: corr_group<17>(sm, tt, wst, acc, eacc); break;
        case 2: corr_group<33>(sm, tt, wst, acc, eacc); break;
        default: corr_group<49>(sm, tt, wst, acc, eacc); break;
    }

    // ---------------- Phase 3: reduce, normalize, store
    float v[16];
#pragma unroll
    for (int i = 0; i < 16; ++i) v[i] = pksum(acc[i]);
#pragma unroll
    for (int e = 0; e < 8; ++e) v[2 * e] += eacc[e];
#pragma unroll
    for (int o = 16; o > 0; o >>= 1) {
#pragma unroll
        for (int i = 0; i < 16; ++i)
            v[i] += __shfl_xor_sync(0xffffffffu, v[i], o);
    }
    if ((tid & 31) == 0) {
        int wid = tid >> 5;
#pragma unroll
        for (int i = 0; i < 16; ++i) red[wid][i] = v[i];
    }
    __syncthreads();
    if (tid < 64) {
        int gg = tid >> 4, dk = tid & 15;   // lag = 16*gg + dk + 1 -> out col = tid
        float sum = red[2 * gg][dk] + red[2 * gg + 1][dk];
        out[(size_t)b * NLAG + tid] = sum * stats[1];
    }
}

extern "C" void kernel_launch(void* const* d_in, const int* in_sizes, int n_in,
                              void* d_out, int out_size)
{
    const float* X = (const float*)d_in[0];
    float* out = (float*)d_out;
    const int B = in_sizes[0] / T_LEN;   // 4096
    autocorr_kernel<<<B, 256>>>(X, out);
}

// round 4
// speedup vs baseline: 1.6297x; 1.6297x over previous
#include <cuda_runtime.h>

typedef unsigned long long ull;

#define T_LEN 8192
#define NLAG  64

// skew2 layout: phys(i) = i + 2*(i>>4)  (stride 18 per 16-elem chunk,
// parity-preserving -> logical-even pairs stay 8B-aligned for LDS.64)
#define PHYS_MAX 9288   // phys(8255)=9285, padded

// ---- 64-bit helpers: smem pair load IS the f32x2 operand (no packs) ----
__device__ __forceinline__ ull lds64(const float* p) {
    return *reinterpret_cast<const ull*>(p);
}
__device__ __forceinline__ void fma2(ull& d, ull a, ull b) {
    asm("fma.rn.f32x2 %0, %1, %2, %0;" : "+l"(d) : "l"(a), "l"(b));
}
__device__ __forceinline__ ull pk(float lo, float hi) {
    ull r;
    asm("mov.b64 %0, {%1, %2};" : "=l"(r) : "f"(lo), "f"(hi));
    return r;
}
__device__ __forceinline__ float2 asf2(ull v) {   // reg-pair alias; MOVs elided
    float2 f;
    asm("mov.b64 {%0, %1}, %2;" : "=f"(f.x), "=f"(f.y) : "l"(v));
    return f;
}
__device__ __forceinline__ float pksum(ull v) {
    float2 f = asf2(v);
    return f.x + f.y;
}

// phys offset of logical index u (compile-time when u is)
#define SKEW(u) ((u) + 2 * ((u) >> 4))

// One lag-group: lags K0..K0+15 (K0 = 1+16g, odd). m-major sliding-window
// schedule: 2 LDS.64 + 1 pack per 16 FMA2, window of 9 live W-pairs.
template<int K0>
__device__ __forceinline__ void corr_group(const float* __restrict__ sm, int tt,
                                           ull* __restrict__ acc,
                                           float* __restrict__ eacc)
{
#pragma unroll 1
    for (int seg = 0; seg < 8; ++seg) {
        const float* p = sm + seg * 1152 + tt * 18;   // phys(seg*1024 + tt*16)

        // W pairs: Wu[r] covers w[2r+1..2r+2] (logical u = K0+2r+1, even -> aligned)
        ull Wu[15];
#pragma unroll
        for (int r = 0; r < 7; ++r) Wu[r] = lds64(p + SKEW(K0 + 2 * r + 1));
        const float w0 = p[SKEW(K0)];                 // w[0]

        float prev_hi = 0.f;     // A[m-1].y carried between steps
#pragma unroll
        for (int m = 0; m < 8; ++m) {
            Wu[m + 7] = lds64(p + SKEW(K0 + 2 * (m + 7) + 1));   // slide window
            const ull   Am = lds64(p + 2 * m);        // aligned A pair (LDS.64, CF)
            const float2 Af = asf2(Am);

            // odd lags dk=2e+1: aligned A x W
#pragma unroll
            for (int e = 0; e < 8; ++e) fma2(acc[2 * e + 1], Am, Wu[m + e]);

            if (m == 0) {
                // wE edges: eacc[e] += a0 * w[2e]  (w[2e] = Wu[e-1].y, e>=1)
                eacc[0] += Af.x * w0;
#pragma unroll
                for (int e = 1; e < 8; ++e) eacc[e] += Af.x * asf2(Wu[e - 1]).y;
            } else {
                // even lags dk=2e: shifted A pair {A[m-1].y, A[m].x} x W[m-1+e]
                const ull Ap = pk(prev_hi, Af.x);
#pragma unroll
                for (int e = 0; e < 8; ++e) fma2(acc[2 * e], Ap, Wu[m - 1 + e]);
            }
            if (m == 7) {
                // wO edges: eacc[e] += a15 * w[15+2e]  (= Wu[e+7].x)
#pragma unroll
                for (int e = 0; e < 8; ++e) eacc[e] += Af.y * asf2(Wu[e + 7]).x;
            }
            prev_hi = Af.y;
        }
    }
}

__global__ __launch_bounds__(256, 3)
void autocorr_kernel(const float* __restrict__ X, float* __restrict__ out)
{
    __shared__ __align__(16) float sm[PHYS_MAX];
    __shared__ float red[8][16];
    __shared__ float wsum[8], wsq[8];
    __shared__ float stats[2];   // [0]=mean, [1]=1/var0

    const int tid = threadIdx.x;
    const int b   = blockIdx.x;
    const float4* Xr = reinterpret_cast<const float4*>(X + (size_t)b * T_LEN);

    // ---------------- Phase 1: load, mean & sumsq, centered skewed store
    float4 xv[8];
    float s = 0.f, q = 0.f;
#pragma unroll
    for (int r = 0; r < 8; ++r) {
        xv[r] = Xr[tid + r * 256];
        s += xv[r].x + xv[r].y + xv[r].z + xv[r].w;
        q += xv[r].x * xv[r].x + xv[r].y * xv[r].y
           + xv[r].z * xv[r].z + xv[r].w * xv[r].w;
    }
#pragma unroll
    for (int o = 16; o > 0; o >>= 1) {
        s += __shfl_xor_sync(0xffffffffu, s, o);
        q += __shfl_xor_sync(0xffffffffu, q, o);
    }
    if ((tid & 31) == 0) { wsum[tid >> 5] = s; wsq[tid >> 5] = q; }
    __syncthreads();
    if (tid == 0) {
        float S = 0.f, Q = 0.f;
#pragma unroll
        for (int i = 0; i < 8; ++i) { S += wsum[i]; Q += wsq[i]; }
        float mean = S * (1.f / (float)T_LEN);
        stats[0] = mean;
        stats[1] = 1.f / (Q - (float)T_LEN * mean * mean);  // 1/T cancels in ratio
    }
    __syncthreads();
    const float mean = stats[0];

#pragma unroll
    for (int r = 0; r < 8; ++r) {
        int i0 = (tid + r * 256) * 4;
        int pp = i0 + 2 * (i0 >> 4);        // all 4 elems share the skew
        *reinterpret_cast<float2*>(&sm[pp])     = make_float2(xv[r].x - mean, xv[r].y - mean);
        *reinterpret_cast<float2*>(&sm[pp + 2]) = make_float2(xv[r].z - mean, xv[r].w - mean);
    }
    if (tid < NLAG) {                       // zero pad -> t<T-k bound handled for free
        int i = T_LEN + tid;
        sm[i + 2 * (i >> 4)] = 0.f;
    }
    __syncthreads();

    // ---------------- Phase 2: lag-group register-tiled correlation
    const int g  = tid >> 6;
    const int tt = tid & 63;

    ull acc[16];
#pragma unroll
    for (int i = 0; i < 16; ++i) acc[i] = 0ull;
    float eacc[8];
#pragma unroll
    for (int i = 0; i < 8; ++i) eacc[i] = 0.f;

    switch (g) {
        case 0: corr_group<1 >(sm, tt, acc, eacc); break;
        case 1: corr_group<17>(sm, tt, acc, eacc); break;
        case 2: corr_group<33>(sm, tt, acc, eacc); break;
        default: corr_group<49>(sm, tt, acc, eacc); break;
    }

    // ---------------- Phase 3: reduce, normalize, store
    float v[16];
#pragma unroll
    for (int i = 0; i < 16; ++i) v[i] = pksum(acc[i]);
#pragma unroll
    for (int e = 0; e < 8; ++e) v[2 * e] += eacc[e];
#pragma unroll
    for (int o = 16; o > 0; o >>= 1) {
#pragma unroll
        for (int i = 0; i < 16; ++i)
            v[i] += __shfl_xor_sync(0xffffffffu, v[i], o);
    }
    if ((tid & 31) == 0) {
        int wid = tid >> 5;
#pragma unroll
        for (int i = 0; i < 16; ++i) red[wid][i] = v[i];
    }
    __syncthreads();
    if (tid < 64) {
        int gg = tid >> 4, dk = tid & 15;   // lag = 16*gg + dk + 1 -> out col = tid
        float sum = red[2 * gg][dk] + red[2 * gg + 1][dk];
        out[(size_t)b * NLAG + tid] = sum * stats[1];
    }
}

extern "C" void kernel_launch(void* const* d_in, const int* in_sizes, int n_in,
                              void* d_out, int out_size)
{
    const float* X = (const float*)d_in[0];
    float* out = (float*)d_out;
    const int B = in_sizes[0] / T_LEN;   // 4096
    autocorr_kernel<<<B, 256>>>(X, out);
}